// round 16
// baseline (speedup 1.0000x reference)
#include <cuda_runtime.h>
#include <cuda_bf16.h>
#include <math.h>
#include <stdint.h>

// ---------------- problem constants ----------------
#define BNODES   4096      // B*N
#define HDIM     256
#define EMAX     16384

// rounded-weight buffer offsets (floats)
#define OFF_IN   0                    // 192*256
#define OFF_MSG  49152                // 256*256
#define OFF_UPD  114688               // 512*256
#define OFF_ADD  245760               // (spacer)
#define OFF_W1   311296               // (spacer)
#define OFF_W2   442368               // 256*256
#define WR_TOTAL 507904
#define RW_BLOCKS ((WR_TOTAL/4 + 255)/256)   // 496
#define W2T_BLK0 (201 + RW_BLOCKS)           // 697

// ---------------- scratch (device globals, no allocs) ----------------
__device__ float g_h   [BNODES*HDIM];
__device__ float g_ht  [BNODES*HDIM];
__device__ float g_P   [BNODES*HDIM];
__device__ float g_agg [BNODES*HDIM];
__device__ float g_agg2[BNODES*HDIM];
__device__ float g_A   [BNODES*HDIM];
__device__ float g_B   [BNODES*HDIM];
__device__ float g_Wr  [WR_TOTAL];
__device__ float g_WAB [2*HDIM*HDIM];
__device__ float g_pa  [64*HDIM];
__device__ float g_pb  [64*HDIM];
__device__ __nv_bfloat16 g_W2T[HDIM*HDIM];
__device__ float g_WfoldT[5*HDIM];
__device__ float g_bfold[8];
__device__ double g_acc;
// CSR by src
__device__ int g_scnt[BNODES + 1];
__device__ int g_srun[BNODES];
__device__ int g_seid[EMAX];

// ---------------- helpers ----------------
__device__ __forceinline__ uint32_t f2tf32(float x) {
    uint32_t r;
    asm("cvt.rna.tf32.f32 %0, %1;" : "=r"(r) : "f"(x));
    return r;
}
__device__ __forceinline__ float roundtf(float x) { return __uint_as_float(f2tf32(x)); }

__device__ __forceinline__ uint32_t f2bf2(float lo, float hi) {
    uint32_t r;
    asm("cvt.rn.bf16x2.f32 %0, %1, %2;" : "=r"(r) : "f"(hi), "f"(lo));
    return r;
}

__device__ __forceinline__ void mma_tf32(float& d0, float& d1, float& d2, float& d3,
                                         uint32_t a0, uint32_t a1, uint32_t a2, uint32_t a3,
                                         uint32_t b0, uint32_t b1)
{
    asm volatile(
        "mma.sync.aligned.m16n8k8.row.col.f32.tf32.tf32.f32 "
        "{%0,%1,%2,%3}, {%4,%5,%6,%7}, {%8,%9}, {%0,%1,%2,%3};"
        : "+f"(d0), "+f"(d1), "+f"(d2), "+f"(d3)
        : "r"(a0), "r"(a1), "r"(a2), "r"(a3), "r"(b0), "r"(b1));
}

__device__ __forceinline__ void mma_bf16(float& d0, float& d1, float& d2, float& d3,
                                         uint32_t a0, uint32_t a1, uint32_t a2, uint32_t a3,
                                         uint32_t b0, uint32_t b1)
{
    asm volatile(
        "mma.sync.aligned.m16n8k16.row.col.f32.bf16.bf16.f32 "
        "{%0,%1,%2,%3}, {%4,%5,%6,%7}, {%8,%9}, {%0,%1,%2,%3};"
        : "+f"(d0), "+f"(d1), "+f"(d2), "+f"(d3)
        : "r"(a0), "r"(a1), "r"(a2), "r"(a3), "r"(b0), "r"(b1));
}

__device__ __forceinline__ void cp_async16(void* smem_ptr, const void* gmem_ptr)
{
    uint32_t s = (uint32_t)__cvta_generic_to_shared(smem_ptr);
    asm volatile("cp.async.cg.shared.global [%0], [%1], 16;" :: "r"(s), "l"(gmem_ptr));
}
__device__ __forceinline__ void cp_commit() { asm volatile("cp.async.commit_group;"); }
template<int N> __device__ __forceinline__ void cp_wait() {
    asm volatile("cp.async.wait_group %0;" :: "n"(N));
}

// ---------------- setup (R14 verbatim) ----------------
__global__ void __launch_bounds__(256)
setup_kernel(const float* __restrict__ W3, const float* __restrict__ b3,
             const float* __restrict__ W_out, const float* __restrict__ b_out,
             const float* __restrict__ props, const float* __restrict__ W_prop,
             const float* __restrict__ b_prop, const float* __restrict__ W_add,
             const float* __restrict__ b_add, const float* __restrict__ b1,
             const float* __restrict__ W_in, const float* __restrict__ W_msg,
             const float* __restrict__ W_upd, const float* __restrict__ W1,
             const float* __restrict__ W2)
{
    int bid = blockIdx.x;
    int tid = threadIdx.x;
    if (bid >= W2T_BLK0) {
        int n0 = (bid - W2T_BLK0) * 4;
        #pragma unroll
        for (int j = 0; j < 4; j++)
            g_W2T[(size_t)(n0 + j)*256 + tid] = __float2bfloat16(W2[(size_t)tid*256 + n0 + j]);
    } else if (bid >= 201) {
        int i = ((bid - 201) * 256 + tid) * 4;
        if (i >= WR_TOTAL) return;
        const float* src;
        int off;
        if      (i < OFF_MSG) { src = W_in;  off = OFF_IN;  }
        else if (i < OFF_UPD) { src = W_msg; off = OFF_MSG; }
        else if (i < OFF_ADD) { src = W_upd; off = OFF_UPD; }
        else if (i < OFF_W1)  { src = W_add; off = OFF_ADD; }
        else if (i < OFF_W2)  { src = W1;    off = OFF_W1;  }
        else                  { src = W2;    off = OFF_W2;  }
        float4 v = *(const float4*)&src[i - off];
        v.x = roundtf(v.x); v.y = roundtf(v.y); v.z = roundtf(v.z); v.w = roundtf(v.w);
        *(float4*)&g_Wr[i] = v;
    } else if (bid < 64) {
        __shared__ float pe[64];
        __shared__ float padd[256];
        if (tid < 64) pe[tid] = props[bid] * W_prop[tid] + b_prop[tid];
        __syncthreads();
        {
            float s = b_add[tid];
            #pragma unroll 8
            for (int p = 0; p < 64; p++) s += pe[p] * W_add[(256 + p)*256 + tid];
            padd[tid] = s;
        }
        __syncthreads();
        float a = b1[tid], b = 0.f;
        for (int t = 0; t < 256; t++) {
            float pv = padd[t];
            a += pv * W1[(size_t)t*256 + tid];
            b += pv * W1[(size_t)(256 + t)*256 + tid];
        }
        g_pa[bid*256 + tid] = a;
        g_pb[bid*256 + tid] = b;
    } else if (bid < 72) {
        int t = (bid - 64)*32 + (tid >> 3);
        int l = tid & 7;
        float s[5] = {0.f,0.f,0.f,0.f,0.f};
        for (int j = l; j < 512; j += 8) {
            float w3 = W3[t*512 + j];
            #pragma unroll
            for (int c = 0; c < 5; c++) s[c] += w3 * W_out[j*5 + c];
        }
        #pragma unroll
        for (int off = 4; off; off >>= 1)
            #pragma unroll
            for (int c = 0; c < 5; c++) s[c] += __shfl_down_sync(0xffffffffu, s[c], off, 8);
        if (l == 0) {
            #pragma unroll
            for (int c = 0; c < 5; c++) g_WfoldT[c*256 + t] = s[c];
        }
    } else if (bid == 72) {
        if (tid < 5) {
            float s = b_out[tid];
            for (int k = 0; k < 512; k++) s += b3[k] * W_out[k*5 + tid];
            g_bfold[tid] = s;
        }
        if (tid == 32) g_acc = 0.0;
    } else {
        int q = bid - 73;
        int isB = q >= 64;
        int k0 = (q & 63) * 4;
        const float* W1p = W1 + (isB ? 256*256 : 0);
        float s0 = 0.f, s1 = 0.f, s2 = 0.f, s3 = 0.f;
        for (int t = 0; t < 256; t++) {
            float w = W1p[(size_t)t*256 + tid];
            s0 += W_add[(k0+0)*256 + t] * w;
            s1 += W_add[(k0+1)*256 + t] * w;
            s2 += W_add[(k0+2)*256 + t] * w;
            s3 += W_add[(k0+3)*256 + t] * w;
        }
        float* dstp = g_WAB + (size_t)isB*65536 + (size_t)k0*256;
        dstp[0*256 + tid] = roundtf(s0);
        dstp[1*256 + tid] = roundtf(s1);
        dstp[2*256 + tid] = roundtf(s2);
        dstp[3*256 + tid] = roundtf(s3);
    }
}

// ---------------- CSR by src (side stream, off critical path) ----------------
__global__ void csr_zero()
{
    int i = blockIdx.x * 256 + threadIdx.x;
    if (i <= BNODES) g_scnt[i] = 0;
    if (i < BNODES)  g_srun[i] = 0;
}
__global__ void csr_count(const int* __restrict__ src, int E)
{
    int i = blockIdx.x * 256 + threadIdx.x;
    if (i < E) atomicAdd(&g_scnt[src[i]], 1);
}
__global__ void __launch_bounds__(1024)
csr_scan()
{
    __shared__ int wsum[32];
    int tid = threadIdx.x;
    int lane = tid & 31, wid = tid >> 5;
    int base = tid * 4;
    int v[4], loc[4], sum = 0;
    #pragma unroll
    for (int q = 0; q < 4; q++) { v[q] = g_scnt[base + q]; loc[q] = sum; sum += v[q]; }
    int inc = sum;
    #pragma unroll
    for (int off = 1; off < 32; off <<= 1) {
        int t = __shfl_up_sync(0xffffffffu, inc, off);
        if (lane >= off) inc += t;
    }
    if (lane == 31) wsum[wid] = inc;
    __syncthreads();
    if (wid == 0) {
        int w = wsum[lane];
        int wi = w;
        #pragma unroll
        for (int off = 1; off < 32; off <<= 1) {
            int t = __shfl_up_sync(0xffffffffu, wi, off);
            if (lane >= off) wi += t;
        }
        wsum[lane] = wi - w;
    }
    __syncthreads();
    int boff = wsum[wid] + (inc - sum);
    #pragma unroll
    for (int q = 0; q < 4; q++) g_scnt[base + q] = boff + loc[q];
    if (tid == 1023) g_scnt[BNODES] = boff + sum;
}
__global__ void csr_fill(const int* __restrict__ src, int E)
{
    int i = blockIdx.x * 256 + threadIdx.x;
    if (i < E) {
        int s = src[i];
        int pos = atomicAdd(&g_srun[s], 1);
        g_seid[g_scnt[s] + pos] = i;
    }
}

// ---------------- tf32 tensor-core SGEMM (R14 verbatim) ----------------
#define APAD 68
#define WPAD 72
template<int CVTA>
__global__ void __launch_bounds__(256)
sgemm_tc(const float* __restrict__ A1, const float* __restrict__ W1, int K1,
         const float* bias, const float* rowBias,
         float* C, int doRelu, int doRound,
         float* __restrict__ zeroBuf, const float* __restrict__ addBuf)
{
    extern __shared__ float sm[];
    float* Asm = sm;
    float* Wsm = sm + 2*64*APAD;

    int tid = threadIdx.x;
    int wid = tid >> 5;
    int lane = tid & 31;
    int warp_m = wid & 1;
    int warp_n = wid >> 1;
    int gi = lane >> 2;
    int tg = lane & 3;

    int m0 = blockIdx.y * 64;
    int n0 = blockIdx.x * 64;

    float acc[2][2][4];
    #pragma unroll
    for (int mt = 0; mt < 2; mt++)
        #pragma unroll
        for (int nt = 0; nt < 2; nt++)
            #pragma unroll
            for (int q = 0; q < 4; q++) acc[mt][nt][q] = 0.f;

    int lr[4], lc[4];
    #pragma unroll
    for (int i = 0; i < 4; i++) { int f = tid + i*256; lr[i] = f >> 4; lc[i] = (f & 15) * 4; }

    const float* A = A1;
    const float* W = W1;
    int K = K1;
    int nit = K >> 6;

    #pragma unroll
    for (int i = 0; i < 4; i++) {
        cp_async16(&Asm[0*64*APAD + lr[i]*APAD + lc[i]],
                   &A[(size_t)(m0 + lr[i])*K + lc[i]]);
        cp_async16(&Wsm[0*64*WPAD + lr[i]*WPAD + lc[i]],
                   &W[(size_t)lr[i]*256 + n0 + lc[i]]);
    }
    cp_commit();

    for (int it = 0; it < nit; it++) {
        int cur = it & 1;
        if (it + 1 < nit) {
            int nb = cur ^ 1;
            int k0n = (it + 1) << 6;
            #pragma unroll
            for (int i = 0; i < 4; i++) {
                cp_async16(&Asm[nb*64*APAD + lr[i]*APAD + lc[i]],
                           &A[(size_t)(m0 + lr[i])*K + k0n + lc[i]]);
                cp_async16(&Wsm[nb*64*WPAD + lr[i]*WPAD + lc[i]],
                           &W[(size_t)(k0n + lr[i])*256 + n0 + lc[i]]);
            }
            cp_commit();
            cp_wait<1>();
        } else {
            cp_wait<0>();
        }
        __syncthreads();

        const float* Ab = Asm + cur*64*APAD;
        const float* Wb = Wsm + cur*64*WPAD;
        #pragma unroll
        for (int kb = 0; kb < 8; kb++) {
            int k8 = kb*8;
            uint32_t a[2][4];
            #pragma unroll
            for (int mt = 0; mt < 2; mt++) {
                int m = warp_m*32 + mt*16 + gi;
                if (CVTA) {
                    a[mt][0] = f2tf32(Ab[(m    )*APAD + k8 + tg    ]);
                    a[mt][1] = f2tf32(Ab[(m + 8)*APAD + k8 + tg    ]);
                    a[mt][2] = f2tf32(Ab[(m    )*APAD + k8 + tg + 4]);
                    a[mt][3] = f2tf32(Ab[(m + 8)*APAD + k8 + tg + 4]);
                } else {
                    a[mt][0] = __float_as_uint(Ab[(m    )*APAD + k8 + tg    ]);
                    a[mt][1] = __float_as_uint(Ab[(m + 8)*APAD + k8 + tg    ]);
                    a[mt][2] = __float_as_uint(Ab[(m    )*APAD + k8 + tg + 4]);
                    a[mt][3] = __float_as_uint(Ab[(m + 8)*APAD + k8 + tg + 4]);
                }
            }
            #pragma unroll
            for (int nt = 0; nt < 2; nt++) {
                int n = warp_n*16 + nt*8 + gi;
                uint32_t b0 = __float_as_uint(Wb[(k8 + tg    )*WPAD + n]);
                uint32_t b1 = __float_as_uint(Wb[(k8 + tg + 4)*WPAD + n]);
                #pragma unroll
                for (int mt = 0; mt < 2; mt++)
                    mma_tf32(acc[mt][nt][0], acc[mt][nt][1], acc[mt][nt][2], acc[mt][nt][3],
                             a[mt][0], a[mt][1], a[mt][2], a[mt][3], b0, b1);
            }
        }
        __syncthreads();
    }

    #pragma unroll
    for (int mt = 0; mt < 2; mt++) {
        #pragma unroll
        for (int half = 0; half < 2; half++) {
            int m = m0 + warp_m*32 + mt*16 + gi + half*8;
            #pragma unroll
            for (int nt = 0; nt < 2; nt++) {
                int n = n0 + warp_n*16 + nt*8 + tg*2;
                float v0 = acc[mt][nt][half*2 + 0];
                float v1 = acc[mt][nt][half*2 + 1];
                if (bias)    { v0 += bias[n]; v1 += bias[n+1]; }
                if (rowBias) {
                    const float* rb = rowBias + ((m >> 6) << 8);
                    v0 += rb[n]; v1 += rb[n+1];
                }
                if (addBuf) {
                    float2 ad = *(const float2*)&addBuf[(size_t)m*256 + n];
                    v0 += ad.x; v1 += ad.y;
                }
                if (doRelu)  { v0 = fmaxf(v0, 0.f); v1 = fmaxf(v1, 0.f); }
                if (doRound) { v0 = roundtf(v0); v1 = roundtf(v1); }
                *(float2*)&C[(size_t)m*256 + n] = make_float2(v0, v1);
                if (zeroBuf) *(float2*)&zeroBuf[(size_t)m*256 + n] = make_float2(0.f, 0.f);
            }
        }
    }
}

// ---------------- fused Hm GEMM + edge scatter ----------------
__global__ void __launch_bounds__(256)
hm_scatter(const float* __restrict__ h, const float* __restrict__ Wmsg_r,
           const float* __restrict__ W_msg, const float* __restrict__ b_msg,
           const int* __restrict__ src, const int* __restrict__ dst,
           const float* __restrict__ ea, float* __restrict__ agg)
{
    extern __shared__ float sm[];
    float* Asm = sm;                   // [2][64][APAD]
    float* Wsm = sm + 2*64*APAD;       // [2][64][WPAD]
    __shared__ float bm_s[64];
    __shared__ float We_s[5][64];

    int tid = threadIdx.x;
    int wid = tid >> 5;
    int lane = tid & 31;
    int warp_m = wid & 1;
    int warp_n = wid >> 1;
    int gi = lane >> 2;
    int tg = lane & 3;

    int m0 = blockIdx.y * 64;
    int n0 = blockIdx.x * 64;

    if (tid < 64) bm_s[tid] = b_msg[n0 + tid];
    for (int i = tid; i < 320; i += 256) {
        int j = i >> 6, c = i & 63;
        We_s[j][c] = W_msg[(size_t)(256 + j)*256 + n0 + c];
    }

    float acc[2][2][4];
    #pragma unroll
    for (int mt = 0; mt < 2; mt++)
        #pragma unroll
        for (int nt = 0; nt < 2; nt++)
            #pragma unroll
            for (int q = 0; q < 4; q++) acc[mt][nt][q] = 0.f;

    int lr[4], lc[4];
    #pragma unroll
    for (int i = 0; i < 4; i++) { int f = tid + i*256; lr[i] = f >> 4; lc[i] = (f & 15) * 4; }

    #pragma unroll
    for (int i = 0; i < 4; i++) {
        cp_async16(&Asm[0*64*APAD + lr[i]*APAD + lc[i]],
                   &h[(size_t)(m0 + lr[i])*256 + lc[i]]);
        cp_async16(&Wsm[0*64*WPAD + lr[i]*WPAD + lc[i]],
                   &Wmsg_r[(size_t)lr[i]*256 + n0 + lc[i]]);
    }
    cp_commit();

    for (int it = 0; it < 4; it++) {
        int cur = it & 1;
        if (it + 1 < 4) {
            int nb = cur ^ 1;
            int k0n = (it + 1) << 6;
            #pragma unroll
            for (int i = 0; i < 4; i++) {
                cp_async16(&Asm[nb*64*APAD + lr[i]*APAD + lc[i]],
                           &h[(size_t)(m0 + lr[i])*256 + k0n + lc[i]]);
                cp_async16(&Wsm[nb*64*WPAD + lr[i]*WPAD + lc[i]],
                           &Wmsg_r[(size_t)(k0n + lr[i])*256 + n0 + lc[i]]);
            }
            cp_commit();
            cp_wait<1>();
        } else {
            cp_wait<0>();
        }
        __syncthreads();

        const float* Ab = Asm + cur*64*APAD;
        const float* Wb = Wsm + cur*64*WPAD;
        #pragma unroll
        for (int kb = 0; kb < 8; kb++) {
            int k8 = kb*8;
            uint32_t a[2][4];
            #pragma unroll
            for (int mt = 0; mt < 2; mt++) {
                int m = warp_m*32 + mt*16 + gi;
                a[mt][0] = __float_as_uint(Ab[(m    )*APAD + k8 + tg    ]);
                a[mt][1] = __float_as_uint(Ab[(m + 8)*APAD + k8 + tg    ]);
                a[mt][2] = __float_as_uint(Ab[(m    )*APAD + k8 + tg + 4]);
                a[mt][3] = __float_as_uint(Ab[(m + 8)*APAD + k8 + tg + 4]);
            }
            #pragma unroll
            for (int nt = 0; nt < 2; nt++) {
                int n = warp_n*16 + nt*8 + gi;
                uint32_t b0 = __float_as_uint(Wb[(k8 + tg    )*WPAD + n]);
                uint32_t b1 = __float_as_uint(Wb[(k8 + tg + 4)*WPAD + n]);
                #pragma unroll
                for (int mt = 0; mt < 2; mt++)
                    mma_tf32(acc[mt][nt][0], acc[mt][nt][1], acc[mt][nt][2], acc[mt][nt][3],
                             a[mt][0], a[mt][1], a[mt][2], a[mt][3], b0, b1);
            }
        }
        __syncthreads();
    }

    // store rounded tile into SMEM: T[64][68]
    float* Ts = Asm;
    #pragma unroll
    for (int mt = 0; mt < 2; mt++) {
        #pragma unroll
        for (int half = 0; half < 2; half++) {
            int r = warp_m*32 + mt*16 + gi + half*8;
            #pragma unroll
            for (int nt = 0; nt < 2; nt++) {
                int c = warp_n*16 + nt*8 + tg*2;
                Ts[r*68 + c]     = roundtf(acc[mt][nt][half*2 + 0]);
                Ts[r*68 + c + 1] = roundtf(acc[mt][nt][half*2 + 1]);
            }
        }
    }
    __syncthreads();

    // scatter this CTA's src-bucket
    int*   stgI = (int*)Wsm;           // [128][8]: row, dst, ea0..4
    float* stgF = Wsm;
    int beg = g_scnt[m0];
    int end = g_scnt[m0 + 64];
    int g = tid >> 6, col = tid & 63;
    for (int c0 = beg; c0 < end; c0 += 128) {
        int nE = min(128, end - c0);
        if (tid < nE) {
            int e = g_seid[c0 + tid];
            stgI[tid*8 + 0] = src[e] - m0;
            stgI[tid*8 + 1] = dst[e];
            const float* eap = ea + (size_t)e*5;
            stgF[tid*8 + 2] = eap[0]; stgF[tid*8 + 3] = eap[1];
            stgF[tid*8 + 4] = eap[2]; stgF[tid*8 + 5] = eap[3];
            stgF[tid*8 + 6] = eap[4];
        }
        __syncthreads();
        for (int q = g; q < nE; q += 4) {
            int row = stgI[q*8 + 0];
            int d   = stgI[q*8 + 1];
            float a0 = stgF[q*8 + 2], a1 = stgF[q*8 + 3], a2 = stgF[q*8 + 4];
            float a3 = stgF[q*8 + 5], a4 = stgF[q*8 + 6];
            float v = bm_s[col]
                    + a0*We_s[0][col] + a1*We_s[1][col] + a2*We_s[2][col]
                    + a3*We_s[3][col] + a4*We_s[4][col]
                    + Ts[row*68 + col];
            v = fmaxf(v, 0.f);
            atomicAdd(&agg[(size_t)d*256 + n0 + col], v);
        }
        __syncthreads();
    }
}

// ---------------- pair megakernel: bf16 MMA (R13 verbatim) ----------------
#define H1W 132
#define WCH 20
__global__ void __launch_bounds__(512, 1)
pair_kernel(const float* __restrict__ Ag, const float* __restrict__ Bg,
            const int* __restrict__ sel_b, const int* __restrict__ sel_i,
            const int* __restrict__ sel_j, const int* __restrict__ golden,
            const __nv_bfloat16* __restrict__ W2T, const float* __restrict__ b2)
{
    extern __shared__ uint32_t smem[];
    uint32_t* h1u = smem;
    uint32_t* w2u = h1u + 128*H1W;
    float*    wfs = (float*)(w2u + 2*256*WCH);
    float*    b2s = wfs + 5*256;
    float*    bfs = b2s + 256;

    int tid  = threadIdx.x;
    int wid  = tid >> 5;
    int lane = tid & 31;
    int warp_m = wid & 3;
    int warp_n = wid >> 2;
    int gi = lane >> 2;
    int tg = lane & 3;
    int e0 = blockIdx.x * 128;

    const char* W2Tb = (const char*)W2T;

    int t_row[2], t_seg[2];
    #pragma unroll
    for (int i = 0; i < 2; i++) { int f = tid + i*512; t_row[i] = f >> 2; t_seg[i] = f & 3; }

    #pragma unroll
    for (int i = 0; i < 2; i++)
        cp_async16(&w2u[0*256*WCH + t_row[i]*WCH + t_seg[i]*4],
                   W2Tb + (size_t)t_row[i]*512 + t_seg[i]*16);
    cp_commit();

    for (int i = tid; i < 5*256; i += 512) wfs[i] = g_WfoldT[i];
    if (tid < 256) b2s[tid] = b2[tid];
    if (tid < 5) bfs[tid] = g_bfold[tid];

    #pragma unroll
    for (int t = 0; t < 8; t++) {
        int r = wid*8 + t;
        int e = e0 + r;
        int bsel = sel_b[e];
        int ii = bsel*64 + sel_i[e];
        int jj = bsel*64 + sel_j[e];
        const float* ap = Ag + (size_t)ii*256;
        const float* bp = Bg + (size_t)jj*256;
        #pragma unroll
        for (int q = 0; q < 2; q++) {
            int c = lane*4 + q*128;
            float4 av = *(const float4*)(ap + c);
            float4 bv = *(const float4*)(bp + c);
            int col = (c >> 1);
            h1u[r*H1W + col    ] = f2bf2(fmaxf(av.x + bv.x, 0.f), fmaxf(av.y + bv.y, 0.f));
            h1u[r*H1W + col + 1] = f2bf2(fmaxf(av.z + bv.z, 0.f), fmaxf(av.w + bv.w, 0.f));
        }
    }

    float acc[2][8][4];
    #pragma unroll
    for (int mt = 0; mt < 2; mt++)
        #pragma unroll
        for (int nt = 0; nt < 8; nt++)
            #pragma unroll
            for (int q = 0; q < 4; q++) acc[mt][nt][q] = 0.f;

    for (int kc = 0; kc < 8; kc++) {
        int cur = kc & 1;
        if (kc + 1 < 8) {
            int nb = cur ^ 1;
            #pragma unroll
            for (int i = 0; i < 2; i++)
                cp_async16(&w2u[nb*256*WCH + t_row[i]*WCH + t_seg[i]*4],
                           W2Tb + (size_t)t_row[i]*512 + (kc + 1)*64 + t_seg[i]*16);
            cp_commit();
            cp_wait<1>();
        } else {
            cp_wait<0>();
        }
        __syncthreads();

        const uint32_t* wb = w2u + cur*256*WCH;
        #pragma unroll
        for (int ks = 0; ks < 2; ks++) {
            int kb = kc*16 + ks*8;
            uint32_t a[2][4];
            #pragma unroll
            for (int mt = 0; mt < 2; mt++) {
                int m = warp_m*32 + mt*16 + gi;
                a[mt][0] = h1u[(m    )*H1W + kb + tg    ];
                a[mt][1] = h1u[(m + 8)*H1W + kb + tg    ];
                a[mt][2] = h1u[(m    )*H1W + kb + tg + 4];
                a[mt][3] = h1u[(m + 8)*H1W + kb + tg + 4];
            }
            #pragma unroll
            for (int nt = 0; nt < 8; nt++) {
                int n = warp_n*64 + nt*8 + gi;
                uint32_t b0 = wb[n*WCH + ks*8 + tg    ];
                uint32_t b1 = wb[n*WCH + ks*8 + tg + 4];
                #pragma unroll
                for (int mt = 0; mt < 2; mt++)
                    mma_bf16(acc[mt][nt][0], acc[mt][nt][1], acc[mt][nt][2], acc[mt][nt][3],
                             a[mt][0], a[mt][1], a[mt][2], a[mt][3], b0, b1);
            }
        }
        __syncthreads();
    }

    #pragma unroll
    for (int mt = 0; mt < 2; mt++) {
        #pragma unroll
        for (int half = 0; half < 2; half++) {
            int m = warp_m*32 + mt*16 + gi + half*8;
            #pragma unroll
            for (int nt = 0; nt < 8; nt++) {
                int n = warp_n*64 + nt*8 + tg*2;
                float v0 = fmaxf(acc[mt][nt][half*2 + 0] + b2s[n],     0.f);
                float v1 = fmaxf(acc[mt][nt][half*2 + 1] + b2s[n + 1], 0.f);
                h1u[m*H1W + (n >> 1)] = f2bf2(v0, v1);
            }
        }
    }
    __syncthreads();

    double lsum = 0.0;
    for (int t = 0; t < 8; t++) {
        int r = wid*8 + t;
        float p[5] = {0.f,0.f,0.f,0.f,0.f};
        #pragma unroll
        for (int m4 = 0; m4 < 4; m4++) {
            int ku = lane + 32*m4;
            uint32_t u = h1u[r*H1W + ku];
            float2 hv = __bfloat1622float2(*reinterpret_cast<__nv_bfloat162*>(&u));
            int k = ku*2;
            #pragma unroll
            for (int c = 0; c < 5; c++)
                p[c] += hv.x * wfs[c*256 + k] + hv.y * wfs[c*256 + k + 1];
        }
        #pragma unroll
        for (int off = 16; off; off >>= 1)
            #pragma unroll
            for (int c = 0; c < 5; c++) p[c] += __shfl_xor_sync(0xffffffffu, p[c], off);
        if (lane == 0) {
            float lg[5], mx = -1e30f;
            #pragma unroll
            for (int c = 0; c < 5; c++) { lg[c] = p[c] + bfs[c]; mx = fmaxf(mx, lg[c]); }
            float s = 0.f;
            #pragma unroll
            for (int c = 0; c < 5; c++) s += expf(lg[c] - mx);
            float lse = mx + logf(s);
            int gold = golden[e0 + r];
            lsum += (double)(lse - lg[gold]);
        }
    }
    if (lane == 0) atomicAdd(&g_acc, lsum);
}

// ---------------- finalize ----------------
__global__ void finalize_kernel(float* __restrict__ out, int esel)
{
    out[0] = (float)(g_acc / (double)esel);
}

// ---------------- host launcher ----------------
extern "C" void kernel_launch(void* const* d_in, const int* in_sizes, int n_in,
                              void* d_out, int out_size)
{
    const float* x         = (const float*)d_in[0];
    const int*   eidx      = (const int*)  d_in[1];
    const float* edge_attr = (const float*)d_in[2];
    const float* props     = (const float*)d_in[3];
    const int*   sel_b     = (const int*)  d_in[4];
    const int*   sel_i     = (const int*)  d_in[5];
    const int*   sel_j     = (const int*)  d_in[6];
    const int*   golden    = (const int*)  d_in[7];
    const float* W_prop = (const float*)d_in[8];
    const float* b_prop = (const float*)d_in[9];
    const float* W_in   = (const float*)d_in[10];
    const float* b_in   = (const float*)d_in[11];
    const float* W_msg  = (const float*)d_in[12];
    const float* b_msg  = (const float*)d_in[13];
    const float* W_upd  = (const float*)d_in[14];
    const float* b_upd  = (const float*)d_in[15];
    const float* W_add  = (const float*)d_in[16];
    const float* b_add  = (const float*)d_in[17];
    const float* W1     = (const float*)d_in[18];
    const float* b1     = (const float*)d_in[19];
    const float* W2     = (const float*)d_in[20];
    const float* b2     = (const float*)d_in[21];
    const float* W3     = (const float*)d_in[22];
    const float* b3     = (const float*)d_in[23];
    const float* W_out  = (const float*)d_in[24];
    const float* b_out  = (const float*)d_in[25];

    int E    = in_sizes[1] / 2;
    int ESEL = in_sizes[4];
    const int* src = eidx;
    const int* dst = eidx + E;

    float *p_h, *p_ht, *p_agg, *p_agg2, *p_A, *p_B, *p_P, *p_Wr, *p_WAB, *p_pa, *p_pb;
    __nv_bfloat16* p_W2T;
    cudaGetSymbolAddress((void**)&p_h,    g_h);
    cudaGetSymbolAddress((void**)&p_ht,   g_ht);
    cudaGetSymbolAddress((void**)&p_agg,  g_agg);
    cudaGetSymbolAddress((void**)&p_agg2, g_agg2);
    cudaGetSymbolAddress((void**)&p_A,    g_A);
    cudaGetSymbolAddress((void**)&p_B,    g_B);
    cudaGetSymbolAddress((void**)&p_P,    g_P);
    cudaGetSymbolAddress((void**)&p_Wr,   g_Wr);
    cudaGetSymbolAddress((void**)&p_WAB,  g_WAB);
    cudaGetSymbolAddress((void**)&p_pa,   g_pa);
    cudaGetSymbolAddress((void**)&p_pb,   g_pb);
    cudaGetSymbolAddress((void**)&p_W2T,  g_W2T);

    int gemmSmem = (2*64*APAD + 2*64*WPAD) * (int)sizeof(float);
    cudaFuncSetAttribute((const void*)sgemm_tc<0>, cudaFuncAttributeMaxDynamicSharedMemorySize, gemmSmem);
    cudaFuncSetAttribute((const void*)sgemm_tc<1>, cudaFuncAttributeMaxDynamicSharedMemorySize, gemmSmem);
    cudaFuncSetAttribute((const void*)hm_scatter, cudaFuncAttributeMaxDynamicSharedMemorySize, gemmSmem);
    int pairSmem = (128*H1W + 2*256*WCH + 5*256 + 256 + 8) * (int)sizeof(uint32_t);
    cudaFuncSetAttribute(pair_kernel, cudaFuncAttributeMaxDynamicSharedMemorySize, pairSmem);

    dim3 gemmGrid(4, BNODES/64);

    const float* Wr_in   = p_Wr + OFF_IN;
    const float* Wr_msg  = p_Wr + OFF_MSG;
    const float* Wr_updT = p_Wr + OFF_UPD;
    const float* Wr_updB = p_Wr + OFF_UPD + 256*256;
    const float* WA_r    = p_WAB;
    const float* WB_r    = p_WAB + 65536;

    cudaStream_t s2;
    cudaStreamCreateWithFlags(&s2, cudaStreamNonBlocking);
    cudaEvent_t evF[5], evJ[5], evC, evS;
    for (int i = 0; i < 5; i++) {
        cudaEventCreateWithFlags(&evF[i], cudaEventDisableTiming);
        cudaEventCreateWithFlags(&evJ[i], cudaEventDisableTiming);
    }
    cudaEventCreateWithFlags(&evC, cudaEventDisableTiming);
    cudaEventCreateWithFlags(&evS, cudaEventDisableTiming);

    // ---- fork s2 from the capturing stream FIRST (required for graph capture) ----
    cudaEventRecord(evS, 0);
    cudaStreamWaitEvent(s2, evS, 0);

    // ---- CSR by src on side stream (concurrent with setup + h0) ----
    csr_zero<<<(BNODES + 256)/256, 256, 0, s2>>>();
    csr_count<<<(E + 255)/256, 256, 0, s2>>>(src, E);
    csr_scan<<<1, 1024, 0, s2>>>();
    csr_fill<<<(E + 255)/256, 256, 0, s2>>>(src, E);
    cudaEventRecord(evC, s2);

    // ---- one-time setup (main) ----
    setup_kernel<<<W2T_BLK0 + 64, 256>>>(W3, b3, W_out, b_out, props, W_prop, b_prop,
                                         W_add, b_add, b1, W_in, W_msg, W_upd, W1, W2);

    // h0 = relu(x @ W_in + b_in), rounded; zeroes agg0
    sgemm_tc<1><<<gemmGrid, 256, gemmSmem>>>(x, Wr_in, 192, b_in, nullptr, p_h, 1, 1,
                                             p_agg, nullptr);

    cudaStreamWaitEvent(0, evC, 0);   // csr ready before first hm_scatter

    float* cur = p_h;
    float* nxt = p_ht;
    float* aggs[2] = { p_agg, p_agg2 };
    for (int t = 0; t < 4; t++) {
        float* aggR = aggs[t & 1];
        float* aggZ = aggs[(t + 1) & 1];

        // fork: side stream computes P = cur@W_upd_top + b_upd (fp32)
        cudaEventRecord(evF[t], 0);
        cudaStreamWaitEvent(s2, evF[t], 0);
        sgemm_tc<0><<<gemmGrid, 256, gemmSmem, s2>>>(cur, Wr_updT, 256, b_upd, nullptr,
                                                     p_P, 0, 0, nullptr, nullptr);
        cudaEventRecord(evJ[t], s2);

        // main: fused Hm GEMM + scatter into aggR
        hm_scatter<<<gemmGrid, 256, gemmSmem>>>(cur, Wr_msg, W_msg, b_msg,
                                                src, dst, edge_attr, aggR);

        // join, then h' = relu(round(aggR)@W_upd_bot + P), rounded; zeroes aggZ
        cudaStreamWaitEvent(0, evJ[t], 0);
        sgemm_tc<1><<<gemmGrid, 256, gemmSmem>>>(aggR, Wr_updB, 256, nullptr, nullptr,
                                                 nxt, 1, 1, aggZ, p_P);
        float* tmp = cur; cur = nxt; nxt = tmp;
    }

    // fork A/B: B = h@WB + pb on s2, A = h@WA + pa on main
    cudaEventRecord(evF[4], 0);
    cudaStreamWaitEvent(s2, evF[4], 0);
    sgemm_tc<0><<<gemmGrid, 256, gemmSmem, s2>>>(cur, WB_r, 256, nullptr, p_pb,
                                                 p_B, 0, 0, nullptr, nullptr);
    cudaEventRecord(evJ[4], s2);
    sgemm_tc<0><<<gemmGrid, 256, gemmSmem>>>(cur, WA_r, 256, nullptr, p_pa,
                                             p_A, 0, 0, nullptr, nullptr);
    cudaStreamWaitEvent(0, evJ[4], 0);

    // pair stage + loss (bf16 MMA)
    pair_kernel<<<ESEL/128, 512, pairSmem>>>(p_A, p_B, sel_b, sel_i, sel_j, golden, p_W2T, b2);

    finalize_kernel<<<1, 1>>>((float*)d_out, ESEL);

    for (int i = 0; i < 5; i++) { cudaEventDestroy(evF[i]); cudaEventDestroy(evJ[i]); }
    cudaEventDestroy(evC);
    cudaEventDestroy(evS);
    cudaStreamDestroy(s2);
}

// round 17
// speedup vs baseline: 1.0346x; 1.0346x over previous
#include <cuda_runtime.h>
#include <cuda_bf16.h>
#include <math.h>
#include <stdint.h>

// ---------------- problem constants ----------------
#define BNODES   4096      // B*N
#define HDIM     256
#define EMAX     16384

// rounded-weight buffer offsets (floats)
#define OFF_IN   0                    // 192*256
#define OFF_MSG  49152                // 256*256
#define OFF_UPD  114688               // 512*256
#define OFF_ADD  245760               // (spacer)
#define OFF_W1   311296               // (spacer)
#define OFF_W2   442368               // 256*256
#define WR_TOTAL 507904
#define RW_BLOCKS ((WR_TOTAL/4 + 255)/256)   // 496
#define SM_RW0   9                           // rounding blocks start
#define SM_W2T0  (9 + RW_BLOCKS)             // 505
#define SM_TOTAL (SM_W2T0 + 64)              // 569

// ---------------- scratch (device globals, no allocs) ----------------
__device__ float g_h   [BNODES*HDIM];
__device__ float g_ht  [BNODES*HDIM];
__device__ float g_Hm  [BNODES*HDIM];
__device__ float g_P   [BNODES*HDIM];
__device__ float g_agg [BNODES*HDIM];
__device__ float g_A   [BNODES*HDIM];
__device__ float g_B   [BNODES*HDIM];
__device__ float g_Wr  [WR_TOTAL];
__device__ float g_WAB [2*HDIM*HDIM];
__device__ float g_pa  [64*HDIM];
__device__ float g_pb  [64*HDIM];
__device__ __nv_bfloat16 g_W2T[HDIM*HDIM];
__device__ float g_WfoldT[5*HDIM];
__device__ float g_bfold[8];
__device__ double g_acc;

// ---------------- helpers ----------------
__device__ __forceinline__ uint32_t f2tf32(float x) {
    uint32_t r;
    asm("cvt.rna.tf32.f32 %0, %1;" : "=r"(r) : "f"(x));
    return r;
}
__device__ __forceinline__ float roundtf(float x) { return __uint_as_float(f2tf32(x)); }

__device__ __forceinline__ uint32_t f2bf2(float lo, float hi) {
    uint32_t r;
    asm("cvt.rn.bf16x2.f32 %0, %1, %2;" : "=r"(r) : "f"(hi), "f"(lo));
    return r;
}

__device__ __forceinline__ void mma_tf32(float& d0, float& d1, float& d2, float& d3,
                                         uint32_t a0, uint32_t a1, uint32_t a2, uint32_t a3,
                                         uint32_t b0, uint32_t b1)
{
    asm volatile(
        "mma.sync.aligned.m16n8k8.row.col.f32.tf32.tf32.f32 "
        "{%0,%1,%2,%3}, {%4,%5,%6,%7}, {%8,%9}, {%0,%1,%2,%3};"
        : "+f"(d0), "+f"(d1), "+f"(d2), "+f"(d3)
        : "r"(a0), "r"(a1), "r"(a2), "r"(a3), "r"(b0), "r"(b1));
}

__device__ __forceinline__ void mma_bf16(float& d0, float& d1, float& d2, float& d3,
                                         uint32_t a0, uint32_t a1, uint32_t a2, uint32_t a3,
                                         uint32_t b0, uint32_t b1)
{
    asm volatile(
        "mma.sync.aligned.m16n8k16.row.col.f32.bf16.bf16.f32 "
        "{%0,%1,%2,%3}, {%4,%5,%6,%7}, {%8,%9}, {%0,%1,%2,%3};"
        : "+f"(d0), "+f"(d1), "+f"(d2), "+f"(d3)
        : "r"(a0), "r"(a1), "r"(a2), "r"(a3), "r"(b0), "r"(b1));
}

__device__ __forceinline__ void cp_async16(void* smem_ptr, const void* gmem_ptr)
{
    uint32_t s = (uint32_t)__cvta_generic_to_shared(smem_ptr);
    asm volatile("cp.async.cg.shared.global [%0], [%1], 16;" :: "r"(s), "l"(gmem_ptr));
}
__device__ __forceinline__ void cp_commit() { asm volatile("cp.async.commit_group;"); }
template<int N> __device__ __forceinline__ void cp_wait() {
    asm volatile("cp.async.wait_group %0;" :: "n"(N));
}

// ---------------- setup_main (critical path): rounding + Wfold + bfold + W2T ----------
__global__ void __launch_bounds__(256)
setup_main(const float* __restrict__ W3, const float* __restrict__ b3,
           const float* __restrict__ W_out, const float* __restrict__ b_out,
           const float* __restrict__ W_in, const float* __restrict__ W_msg,
           const float* __restrict__ W_upd, const float* __restrict__ W_add,
           const float* __restrict__ W1, const float* __restrict__ W2)
{
    int bid = blockIdx.x;
    int tid = threadIdx.x;
    if (bid >= SM_W2T0) {
        int n0 = (bid - SM_W2T0) * 4;
        #pragma unroll
        for (int j = 0; j < 4; j++)
            g_W2T[(size_t)(n0 + j)*256 + tid] = __float2bfloat16(W2[(size_t)tid*256 + n0 + j]);
    } else if (bid >= SM_RW0) {
        int i = ((bid - SM_RW0) * 256 + tid) * 4;
        if (i >= WR_TOTAL) return;
        const float* src;
        int off;
        if      (i < OFF_MSG) { src = W_in;  off = OFF_IN;  }
        else if (i < OFF_UPD) { src = W_msg; off = OFF_MSG; }
        else if (i < OFF_ADD) { src = W_upd; off = OFF_UPD; }
        else if (i < OFF_W1)  { src = W_add; off = OFF_ADD; }
        else if (i < OFF_W2)  { src = W1;    off = OFF_W1;  }
        else                  { src = W2;    off = OFF_W2;  }
        float4 v = *(const float4*)&src[i - off];
        v.x = roundtf(v.x); v.y = roundtf(v.y); v.z = roundtf(v.z); v.w = roundtf(v.w);
        *(float4*)&g_Wr[i] = v;
    } else if (bid < 8) {
        int t = bid*32 + (tid >> 3);
        int l = tid & 7;
        float s[5] = {0.f,0.f,0.f,0.f,0.f};
        for (int j = l; j < 512; j += 8) {
            float w3 = W3[t*512 + j];
            #pragma unroll
            for (int c = 0; c < 5; c++) s[c] += w3 * W_out[j*5 + c];
        }
        #pragma unroll
        for (int off = 4; off; off >>= 1)
            #pragma unroll
            for (int c = 0; c < 5; c++) s[c] += __shfl_down_sync(0xffffffffu, s[c], off, 8);
        if (l == 0) {
            #pragma unroll
            for (int c = 0; c < 5; c++) g_WfoldT[c*256 + t] = s[c];
        }
    } else {
        if (tid < 5) {
            float s = b_out[tid];
            for (int k = 0; k < 512; k++) s += b3[k] * W_out[k*5 + tid];
            g_bfold[tid] = s;
        }
        if (tid == 32) g_acc = 0.0;
    }
}

// ---------------- setup_side (s2): pa/pb + WA/WB ----------------
__global__ void __launch_bounds__(256)
setup_side(const float* __restrict__ props, const float* __restrict__ W_prop,
           const float* __restrict__ b_prop, const float* __restrict__ W_add,
           const float* __restrict__ b_add, const float* __restrict__ b1,
           const float* __restrict__ W1)
{
    int bid = blockIdx.x;
    int tid = threadIdx.x;
    if (bid < 64) {
        __shared__ float pe[64];
        __shared__ float padd[256];
        if (tid < 64) pe[tid] = props[bid] * W_prop[tid] + b_prop[tid];
        __syncthreads();
        {
            float s = b_add[tid];
            #pragma unroll 8
            for (int p = 0; p < 64; p++) s += pe[p] * W_add[(256 + p)*256 + tid];
            padd[tid] = s;
        }
        __syncthreads();
        float a = b1[tid], b = 0.f;
        for (int t = 0; t < 256; t++) {
            float pv = padd[t];
            a += pv * W1[(size_t)t*256 + tid];
            b += pv * W1[(size_t)(256 + t)*256 + tid];
        }
        g_pa[bid*256 + tid] = a;
        g_pb[bid*256 + tid] = b;
    } else {
        int q = bid - 64;            // 0..127
        int isB = q >= 64;
        int k0 = (q & 63) * 4;
        const float* W1p = W1 + (isB ? 256*256 : 0);
        float s0 = 0.f, s1 = 0.f, s2 = 0.f, s3 = 0.f;
        for (int t = 0; t < 256; t++) {
            float w = W1p[(size_t)t*256 + tid];
            s0 += W_add[(k0+0)*256 + t] * w;
            s1 += W_add[(k0+1)*256 + t] * w;
            s2 += W_add[(k0+2)*256 + t] * w;
            s3 += W_add[(k0+3)*256 + t] * w;
        }
        float* dstp = g_WAB + (size_t)isB*65536 + (size_t)k0*256;
        dstp[0*256 + tid] = roundtf(s0);
        dstp[1*256 + tid] = roundtf(s1);
        dstp[2*256 + tid] = roundtf(s2);
        dstp[3*256 + tid] = roundtf(s3);
    }
}

// ---------------- edge scatter (R14 verbatim) ----------------
__global__ void __launch_bounds__(256)
edge_scatter(const int* __restrict__ src, const int* __restrict__ dst,
             const float* __restrict__ ea, const float* __restrict__ W_msg,
             const float* __restrict__ b_msg, const float* __restrict__ Hm,
             float* __restrict__ agg, int E)
{
    __shared__ float We[5][256];
    __shared__ float bm[256];
    __shared__ float eas[32][5];
    __shared__ int   ss[32], ds[32];
    int tid = threadIdx.x;
    const float* Wep = W_msg + 256*256;
    for (int i = tid; i < 5*256; i += 256) ((float*)We)[i] = Wep[i];
    bm[tid] = b_msg[tid];
    int e0 = blockIdx.x * 32;
    if (tid < 32 && e0 + tid < E) { ss[tid] = src[e0+tid]; ds[tid] = dst[e0+tid]; }
    if (tid >= 64 && tid < 64 + 160) {
        int i = tid - 64;
        if ((size_t)e0*5 + i < (size_t)E*5) eas[i/5][i%5] = ea[(size_t)e0*5 + i];
    }
    __syncthreads();
    #pragma unroll 4
    for (int q = 0; q < 32; q++) {
        int e = e0 + q;
        if (e >= E) break;
        float v = bm[tid]
                + eas[q][0]*We[0][tid] + eas[q][1]*We[1][tid] + eas[q][2]*We[2][tid]
                + eas[q][3]*We[3][tid] + eas[q][4]*We[4][tid]
                + Hm[(size_t)ss[q]*256 + tid];
        v = fmaxf(v, 0.f);
        atomicAdd(&agg[(size_t)ds[q]*256 + tid], v);
    }
}

// ---------------- tf32 tensor-core SGEMM (R14 verbatim) ----------------
#define APAD 68
#define WPAD 72
template<int CVTA>
__global__ void __launch_bounds__(256)
sgemm_tc(const float* __restrict__ A1, const float* __restrict__ W1, int K1,
         const float* bias, const float* rowBias,
         float* C, int doRelu, int doRound,
         float* __restrict__ zeroBuf, const float* __restrict__ addBuf)
{
    extern __shared__ float sm[];
    float* Asm = sm;
    float* Wsm = sm + 2*64*APAD;

    int tid = threadIdx.x;
    int wid = tid >> 5;
    int lane = tid & 31;
    int warp_m = wid & 1;
    int warp_n = wid >> 1;
    int gi = lane >> 2;
    int tg = lane & 3;

    int m0 = blockIdx.y * 64;
    int n0 = blockIdx.x * 64;

    float acc[2][2][4];
    #pragma unroll
    for (int mt = 0; mt < 2; mt++)
        #pragma unroll
        for (int nt = 0; nt < 2; nt++)
            #pragma unroll
            for (int q = 0; q < 4; q++) acc[mt][nt][q] = 0.f;

    int lr[4], lc[4];
    #pragma unroll
    for (int i = 0; i < 4; i++) { int f = tid + i*256; lr[i] = f >> 4; lc[i] = (f & 15) * 4; }

    const float* A = A1;
    const float* W = W1;
    int K = K1;
    int nit = K >> 6;

    #pragma unroll
    for (int i = 0; i < 4; i++) {
        cp_async16(&Asm[0*64*APAD + lr[i]*APAD + lc[i]],
                   &A[(size_t)(m0 + lr[i])*K + lc[i]]);
        cp_async16(&Wsm[0*64*WPAD + lr[i]*WPAD + lc[i]],
                   &W[(size_t)lr[i]*256 + n0 + lc[i]]);
    }
    cp_commit();

    for (int it = 0; it < nit; it++) {
        int cur = it & 1;
        if (it + 1 < nit) {
            int nb = cur ^ 1;
            int k0n = (it + 1) << 6;
            #pragma unroll
            for (int i = 0; i < 4; i++) {
                cp_async16(&Asm[nb*64*APAD + lr[i]*APAD + lc[i]],
                           &A[(size_t)(m0 + lr[i])*K + k0n + lc[i]]);
                cp_async16(&Wsm[nb*64*WPAD + lr[i]*WPAD + lc[i]],
                           &W[(size_t)(k0n + lr[i])*256 + n0 + lc[i]]);
            }
            cp_commit();
            cp_wait<1>();
        } else {
            cp_wait<0>();
        }
        __syncthreads();

        const float* Ab = Asm + cur*64*APAD;
        const float* Wb = Wsm + cur*64*WPAD;
        #pragma unroll
        for (int kb = 0; kb < 8; kb++) {
            int k8 = kb*8;
            uint32_t a[2][4];
            #pragma unroll
            for (int mt = 0; mt < 2; mt++) {
                int m = warp_m*32 + mt*16 + gi;
                if (CVTA) {
                    a[mt][0] = f2tf32(Ab[(m    )*APAD + k8 + tg    ]);
                    a[mt][1] = f2tf32(Ab[(m + 8)*APAD + k8 + tg    ]);
                    a[mt][2] = f2tf32(Ab[(m    )*APAD + k8 + tg + 4]);
                    a[mt][3] = f2tf32(Ab[(m + 8)*APAD + k8 + tg + 4]);
                } else {
                    a[mt][0] = __float_as_uint(Ab[(m    )*APAD + k8 + tg    ]);
                    a[mt][1] = __float_as_uint(Ab[(m + 8)*APAD + k8 + tg    ]);
                    a[mt][2] = __float_as_uint(Ab[(m    )*APAD + k8 + tg + 4]);
                    a[mt][3] = __float_as_uint(Ab[(m + 8)*APAD + k8 + tg + 4]);
                }
            }
            #pragma unroll
            for (int nt = 0; nt < 2; nt++) {
                int n = warp_n*16 + nt*8 + gi;
                uint32_t b0 = __float_as_uint(Wb[(k8 + tg    )*WPAD + n]);
                uint32_t b1 = __float_as_uint(Wb[(k8 + tg + 4)*WPAD + n]);
                #pragma unroll
                for (int mt = 0; mt < 2; mt++)
                    mma_tf32(acc[mt][nt][0], acc[mt][nt][1], acc[mt][nt][2], acc[mt][nt][3],
                             a[mt][0], a[mt][1], a[mt][2], a[mt][3], b0, b1);
            }
        }
        __syncthreads();
    }

    #pragma unroll
    for (int mt = 0; mt < 2; mt++) {
        #pragma unroll
        for (int half = 0; half < 2; half++) {
            int m = m0 + warp_m*32 + mt*16 + gi + half*8;
            #pragma unroll
            for (int nt = 0; nt < 2; nt++) {
                int n = n0 + warp_n*16 + nt*8 + tg*2;
                float v0 = acc[mt][nt][half*2 + 0];
                float v1 = acc[mt][nt][half*2 + 1];
                if (bias)    { v0 += bias[n]; v1 += bias[n+1]; }
                if (rowBias) {
                    const float* rb = rowBias + ((m >> 6) << 8);
                    v0 += rb[n]; v1 += rb[n+1];
                }
                if (addBuf) {
                    float2 ad = *(const float2*)&addBuf[(size_t)m*256 + n];
                    v0 += ad.x; v1 += ad.y;
                }
                if (doRelu)  { v0 = fmaxf(v0, 0.f); v1 = fmaxf(v1, 0.f); }
                if (doRound) { v0 = roundtf(v0); v1 = roundtf(v1); }
                *(float2*)&C[(size_t)m*256 + n] = make_float2(v0, v1);
                if (zeroBuf) *(float2*)&zeroBuf[(size_t)m*256 + n] = make_float2(0.f, 0.f);
            }
        }
    }
}

// ---------------- pair megakernel: bf16 MMA (R13 verbatim) ----------------
#define H1W 132
#define WCH 20
__global__ void __launch_bounds__(512, 1)
pair_kernel(const float* __restrict__ Ag, const float* __restrict__ Bg,
            const int* __restrict__ sel_b, const int* __restrict__ sel_i,
            const int* __restrict__ sel_j, const int* __restrict__ golden,
            const __nv_bfloat16* __restrict__ W2T, const float* __restrict__ b2)
{
    extern __shared__ uint32_t smem[];
    uint32_t* h1u = smem;
    uint32_t* w2u = h1u + 128*H1W;
    float*    wfs = (float*)(w2u + 2*256*WCH);
    float*    b2s = wfs + 5*256;
    float*    bfs = b2s + 256;

    int tid  = threadIdx.x;
    int wid  = tid >> 5;
    int lane = tid & 31;
    int warp_m = wid & 3;
    int warp_n = wid >> 2;
    int gi = lane >> 2;
    int tg = lane & 3;
    int e0 = blockIdx.x * 128;

    const char* W2Tb = (const char*)W2T;

    int t_row[2], t_seg[2];
    #pragma unroll
    for (int i = 0; i < 2; i++) { int f = tid + i*512; t_row[i] = f >> 2; t_seg[i] = f & 3; }

    #pragma unroll
    for (int i = 0; i < 2; i++)
        cp_async16(&w2u[0*256*WCH + t_row[i]*WCH + t_seg[i]*4],
                   W2Tb + (size_t)t_row[i]*512 + t_seg[i]*16);
    cp_commit();

    for (int i = tid; i < 5*256; i += 512) wfs[i] = g_WfoldT[i];
    if (tid < 256) b2s[tid] = b2[tid];
    if (tid < 5) bfs[tid] = g_bfold[tid];

    #pragma unroll
    for (int t = 0; t < 8; t++) {
        int r = wid*8 + t;
        int e = e0 + r;
        int bsel = sel_b[e];
        int ii = bsel*64 + sel_i[e];
        int jj = bsel*64 + sel_j[e];
        const float* ap = Ag + (size_t)ii*256;
        const float* bp = Bg + (size_t)jj*256;
        #pragma unroll
        for (int q = 0; q < 2; q++) {
            int c = lane*4 + q*128;
            float4 av = *(const float4*)(ap + c);
            float4 bv = *(const float4*)(bp + c);
            int col = (c >> 1);
            h1u[r*H1W + col    ] = f2bf2(fmaxf(av.x + bv.x, 0.f), fmaxf(av.y + bv.y, 0.f));
            h1u[r*H1W + col + 1] = f2bf2(fmaxf(av.z + bv.z, 0.f), fmaxf(av.w + bv.w, 0.f));
        }
    }

    float acc[2][8][4];
    #pragma unroll
    for (int mt = 0; mt < 2; mt++)
        #pragma unroll
        for (int nt = 0; nt < 8; nt++)
            #pragma unroll
            for (int q = 0; q < 4; q++) acc[mt][nt][q] = 0.f;

    for (int kc = 0; kc < 8; kc++) {
        int cur = kc & 1;
        if (kc + 1 < 8) {
            int nb = cur ^ 1;
            #pragma unroll
            for (int i = 0; i < 2; i++)
                cp_async16(&w2u[nb*256*WCH + t_row[i]*WCH + t_seg[i]*4],
                           W2Tb + (size_t)t_row[i]*512 + (kc + 1)*64 + t_seg[i]*16);
            cp_commit();
            cp_wait<1>();
        } else {
            cp_wait<0>();
        }
        __syncthreads();

        const uint32_t* wb = w2u + cur*256*WCH;
        #pragma unroll
        for (int ks = 0; ks < 2; ks++) {
            int kb = kc*16 + ks*8;
            uint32_t a[2][4];
            #pragma unroll
            for (int mt = 0; mt < 2; mt++) {
                int m = warp_m*32 + mt*16 + gi;
                a[mt][0] = h1u[(m    )*H1W + kb + tg    ];
                a[mt][1] = h1u[(m + 8)*H1W + kb + tg    ];
                a[mt][2] = h1u[(m    )*H1W + kb + tg + 4];
                a[mt][3] = h1u[(m + 8)*H1W + kb + tg + 4];
            }
            #pragma unroll
            for (int nt = 0; nt < 8; nt++) {
                int n = warp_n*64 + nt*8 + gi;
                uint32_t b0 = wb[n*WCH + ks*8 + tg    ];
                uint32_t b1 = wb[n*WCH + ks*8 + tg + 4];
                #pragma unroll
                for (int mt = 0; mt < 2; mt++)
                    mma_bf16(acc[mt][nt][0], acc[mt][nt][1], acc[mt][nt][2], acc[mt][nt][3],
                             a[mt][0], a[mt][1], a[mt][2], a[mt][3], b0, b1);
            }
        }
        __syncthreads();
    }

    #pragma unroll
    for (int mt = 0; mt < 2; mt++) {
        #pragma unroll
        for (int half = 0; half < 2; half++) {
            int m = warp_m*32 + mt*16 + gi + half*8;
            #pragma unroll
            for (int nt = 0; nt < 8; nt++) {
                int n = warp_n*64 + nt*8 + tg*2;
                float v0 = fmaxf(acc[mt][nt][half*2 + 0] + b2s[n],     0.f);
                float v1 = fmaxf(acc[mt][nt][half*2 + 1] + b2s[n + 1], 0.f);
                h1u[m*H1W + (n >> 1)] = f2bf2(v0, v1);
            }
        }
    }
    __syncthreads();

    double lsum = 0.0;
    for (int t = 0; t < 8; t++) {
        int r = wid*8 + t;
        float p[5] = {0.f,0.f,0.f,0.f,0.f};
        #pragma unroll
        for (int m4 = 0; m4 < 4; m4++) {
            int ku = lane + 32*m4;
            uint32_t u = h1u[r*H1W + ku];
            float2 hv = __bfloat1622float2(*reinterpret_cast<__nv_bfloat162*>(&u));
            int k = ku*2;
            #pragma unroll
            for (int c = 0; c < 5; c++)
                p[c] += hv.x * wfs[c*256 + k] + hv.y * wfs[c*256 + k + 1];
        }
        #pragma unroll
        for (int off = 16; off; off >>= 1)
            #pragma unroll
            for (int c = 0; c < 5; c++) p[c] += __shfl_xor_sync(0xffffffffu, p[c], off);
        if (lane == 0) {
            float lg[5], mx = -1e30f;
            #pragma unroll
            for (int c = 0; c < 5; c++) { lg[c] = p[c] + bfs[c]; mx = fmaxf(mx, lg[c]); }
            float s = 0.f;
            #pragma unroll
            for (int c = 0; c < 5; c++) s += expf(lg[c] - mx);
            float lse = mx + logf(s);
            int gold = golden[e0 + r];
            lsum += (double)(lse - lg[gold]);
        }
    }
    if (lane == 0) atomicAdd(&g_acc, lsum);
}

// ---------------- finalize ----------------
__global__ void finalize_kernel(float* __restrict__ out, int esel)
{
    out[0] = (float)(g_acc / (double)esel);
}

// ---------------- host launcher (dual-stream fork/join, graph-capturable) ------------
extern "C" void kernel_launch(void* const* d_in, const int* in_sizes, int n_in,
                              void* d_out, int out_size)
{
    const float* x         = (const float*)d_in[0];
    const int*   eidx      = (const int*)  d_in[1];
    const float* edge_attr = (const float*)d_in[2];
    const float* props     = (const float*)d_in[3];
    const int*   sel_b     = (const int*)  d_in[4];
    const int*   sel_i     = (const int*)  d_in[5];
    const int*   sel_j     = (const int*)  d_in[6];
    const int*   golden    = (const int*)  d_in[7];
    const float* W_prop = (const float*)d_in[8];
    const float* b_prop = (const float*)d_in[9];
    const float* W_in   = (const float*)d_in[10];
    const float* b_in   = (const float*)d_in[11];
    const float* W_msg  = (const float*)d_in[12];
    const float* b_msg  = (const float*)d_in[13];
    const float* W_upd  = (const float*)d_in[14];
    const float* b_upd  = (const float*)d_in[15];
    const float* W_add  = (const float*)d_in[16];
    const float* b_add  = (const float*)d_in[17];
    const float* W1     = (const float*)d_in[18];
    const float* b1     = (const float*)d_in[19];
    const float* W2     = (const float*)d_in[20];
    const float* b2     = (const float*)d_in[21];
    const float* W3     = (const float*)d_in[22];
    const float* b3     = (const float*)d_in[23];
    const float* W_out  = (const float*)d_in[24];
    const float* b_out  = (const float*)d_in[25];

    int E    = in_sizes[1] / 2;
    int ESEL = in_sizes[4];
    const int* src = eidx;
    const int* dst = eidx + E;

    float *p_h, *p_ht, *p_agg, *p_A, *p_B, *p_Hm, *p_P, *p_Wr, *p_WAB, *p_pa, *p_pb;
    __nv_bfloat16* p_W2T;
    cudaGetSymbolAddress((void**)&p_h,    g_h);
    cudaGetSymbolAddress((void**)&p_ht,   g_ht);
    cudaGetSymbolAddress((void**)&p_agg,  g_agg);
    cudaGetSymbolAddress((void**)&p_A,    g_A);
    cudaGetSymbolAddress((void**)&p_B,    g_B);
    cudaGetSymbolAddress((void**)&p_Hm,   g_Hm);
    cudaGetSymbolAddress((void**)&p_P,    g_P);
    cudaGetSymbolAddress((void**)&p_Wr,   g_Wr);
    cudaGetSymbolAddress((void**)&p_WAB,  g_WAB);
    cudaGetSymbolAddress((void**)&p_pa,   g_pa);
    cudaGetSymbolAddress((void**)&p_pb,   g_pb);
    cudaGetSymbolAddress((void**)&p_W2T,  g_W2T);

    int gemmSmem = (2*64*APAD + 2*64*WPAD) * (int)sizeof(float);
    cudaFuncSetAttribute((const void*)sgemm_tc<0>, cudaFuncAttributeMaxDynamicSharedMemorySize, gemmSmem);
    cudaFuncSetAttribute((const void*)sgemm_tc<1>, cudaFuncAttributeMaxDynamicSharedMemorySize, gemmSmem);
    int pairSmem = (128*H1W + 2*256*WCH + 5*256 + 256 + 8) * (int)sizeof(uint32_t);
    cudaFuncSetAttribute(pair_kernel, cudaFuncAttributeMaxDynamicSharedMemorySize, pairSmem);

    dim3 gemmGrid(4, BNODES/64);

    const float* Wr_in   = p_Wr + OFF_IN;
    const float* Wr_msg  = p_Wr + OFF_MSG;
    const float* Wr_updT = p_Wr + OFF_UPD;
    const float* Wr_updB = p_Wr + OFF_UPD + 256*256;
    const float* WA_r    = p_WAB;
    const float* WB_r    = p_WAB + 65536;

    cudaStream_t s2;
    cudaStreamCreateWithFlags(&s2, cudaStreamNonBlocking);
    cudaEvent_t evF[5], evJ[5], evS, evW;
    for (int i = 0; i < 5; i++) {
        cudaEventCreateWithFlags(&evF[i], cudaEventDisableTiming);
        cudaEventCreateWithFlags(&evJ[i], cudaEventDisableTiming);
    }
    cudaEventCreateWithFlags(&evS, cudaEventDisableTiming);
    cudaEventCreateWithFlags(&evW, cudaEventDisableTiming);

    // ---- fork s2 from the capturing stream FIRST ----
    cudaEventRecord(evS, 0);
    cudaStreamWaitEvent(s2, evS, 0);

    // ---- side-stream setup: pa/pb + WA/WB (needed only by A/B GEMMs at the end) ----
    setup_side<<<192, 256, 0, s2>>>(props, W_prop, b_prop, W_add, b_add, b1, W1);
    cudaEventRecord(evW, s2);

    // ---- critical-path setup: weight rounding + Wfold + bfold + W2T ----
    setup_main<<<SM_TOTAL, 256>>>(W3, b3, W_out, b_out, W_in, W_msg, W_upd, W_add, W1, W2);

    // h0 = relu(x @ W_in + b_in), rounded (x unrounded -> CVTA=1); zeroes agg
    sgemm_tc<1><<<gemmGrid, 256, gemmSmem>>>(x, Wr_in, 192, b_in, nullptr, p_h, 1, 1,
                                             p_agg, nullptr);

    float* cur = p_h;
    float* nxt = p_ht;
    for (int t = 0; t < 4; t++) {
        // fork: side stream computes P = cur@W_upd_top + b_upd (fp32)
        cudaEventRecord(evF[t], 0);
        cudaStreamWaitEvent(s2, evF[t], 0);
        sgemm_tc<0><<<gemmGrid, 256, gemmSmem, s2>>>(cur, Wr_updT, 256, b_upd, nullptr,
                                                     p_P, 0, 0, nullptr, nullptr);
        cudaEventRecord(evJ[t], s2);

        // main: Hm = round(cur@W_msg); then scatter into agg
        sgemm_tc<0><<<gemmGrid, 256, gemmSmem>>>(cur, Wr_msg, 256, nullptr, nullptr,
                                                 p_Hm, 0, 1, nullptr, nullptr);
        edge_scatter<<<(E + 31)/32, 256>>>(src, dst, edge_attr, W_msg, b_msg, p_Hm, p_agg, E);

        // join, then h' = relu(round(agg)@W_upd_bot + P), rounded; zeroes agg for next round
        cudaStreamWaitEvent(0, evJ[t], 0);
        sgemm_tc<1><<<gemmGrid, 256, gemmSmem>>>(p_agg, Wr_updB, 256, nullptr, nullptr,
                                                 nxt, 1, 1, p_agg, p_P);
        float* tmp = cur; cur = nxt; nxt = tmp;
    }

    // join setup_side before A/B GEMMs
    cudaStreamWaitEvent(0, evW, 0);

    // fork A/B: B = h@WB + pb on s2, A = h@WA + pa on main
    cudaEventRecord(evF[4], 0);
    cudaStreamWaitEvent(s2, evF[4], 0);
    sgemm_tc<0><<<gemmGrid, 256, gemmSmem, s2>>>(cur, WB_r, 256, nullptr, p_pb,
                                                 p_B, 0, 0, nullptr, nullptr);
    cudaEventRecord(evJ[4], s2);
    sgemm_tc<0><<<gemmGrid, 256, gemmSmem>>>(cur, WA_r, 256, nullptr, p_pa,
                                             p_A, 0, 0, nullptr, nullptr);
    cudaStreamWaitEvent(0, evJ[4], 0);

    // pair stage + loss (bf16 MMA)
    pair_kernel<<<ESEL/128, 512, pairSmem>>>(p_A, p_B, sel_b, sel_i, sel_j, golden, p_W2T, b2);

    finalize_kernel<<<1, 1>>>((float*)d_out, ESEL);

    for (int i = 0; i < 5; i++) { cudaEventDestroy(evF[i]); cudaEventDestroy(evJ[i]); }
    cudaEventDestroy(evS);
    cudaEventDestroy(evW);
    cudaStreamDestroy(s2);
}